// round 8
// baseline (speedup 1.0000x reference)
#include <cuda_runtime.h>
#include <cuda_bf16.h>

// Problem constants (fixed by the reference)
constexpr int NN = 40000;   // nodes
constexpr int NE = 640000;  // edges
constexpr int DD = 128;     // feature dim
constexpr int NG = 64;      // graphs

constexpr int SCAN_B = 1024;
constexpr int NSCAN  = (NN + SCAN_B) / SCAN_B;  // 40 blocks

// ---------------- scratch (static device globals; no allocations) ----------------
__device__ __nv_bfloat16 g_hb [NN * DD];  // gemm1 out (unscaled, bf16)
__device__ __nv_bfloat16 g_x2b[NN * DD];  // agg1 out (dinv-prescaled relu, bf16)
__device__ float g_zsum[NG * DD];         // per-graph feature sums (REDG target)
__device__ int   g_deg[NN];               // in-degree (without self loop)
__device__ float g_dinv[NN];              // 1/sqrt(deg+1)
__device__ int   g_rowptr[NN + 1];        // CSR row pointers (by dst)
__device__ int   g_cnt[NN];               // fill cursors
__device__ int   g_csr[NE];               // CSR column indices (src node per edge)
__device__ int   g_bsum[64];              // scan block sums (NSCAN=40 used)

// ---------------- packed f32x2 helpers ----------------
__device__ __forceinline__ unsigned long long pack2(float lo, float hi) {
    unsigned long long r;
    asm("mov.b64 %0, {%1, %2};" : "=l"(r) : "f"(lo), "f"(hi));
    return r;
}
__device__ __forceinline__ void unpack2(unsigned long long v, float& lo, float& hi) {
    asm("mov.b64 {%0, %1}, %2;" : "=f"(lo), "=f"(hi) : "l"(v));
}
__device__ __forceinline__ unsigned long long fma2(unsigned long long a,
                                                   unsigned long long b,
                                                   unsigned long long c) {
    unsigned long long d;
    asm("fma.rn.f32x2 %0, %1, %2, %3;" : "=l"(d) : "l"(a), "l"(b), "l"(c));
    return d;
}

// ---------------- bf16x4 helpers ----------------
__device__ __forceinline__ float4 bf4_to_f4(uint2 p) {
    __nv_bfloat162 a = *reinterpret_cast<__nv_bfloat162*>(&p.x);
    __nv_bfloat162 b = *reinterpret_cast<__nv_bfloat162*>(&p.y);
    float2 f0 = __bfloat1622float2(a);
    float2 f1 = __bfloat1622float2(b);
    return make_float4(f0.x, f0.y, f1.x, f1.y);
}
__device__ __forceinline__ uint2 f4_to_bf4(float4 v) {
    __nv_bfloat162 a = __float22bfloat162_rn(make_float2(v.x, v.y));
    __nv_bfloat162 b = __float22bfloat162_rn(make_float2(v.z, v.w));
    uint2 r;
    r.x = *reinterpret_cast<unsigned*>(&a);
    r.y = *reinterpret_cast<unsigned*>(&b);
    return r;
}

// ---------------- CSR construction ----------------
__global__ void hist_kernel(const int* __restrict__ dst) {
    int i = blockIdx.x * blockDim.x + threadIdx.x;
    if (i < NE) atomicAdd(&g_deg[dst[i]], 1);
}

__global__ void __launch_bounds__(SCAN_B) scan1_kernel() {
    __shared__ int wsum[32];
    int tid = threadIdx.x, lane = tid & 31, wid = tid >> 5;
    int i = blockIdx.x * SCAN_B + tid;
    int v = (i < NN) ? g_deg[i] : 0;
    int inc = v;
#pragma unroll
    for (int off = 1; off < 32; off <<= 1) {
        int n = __shfl_up_sync(0xFFFFFFFFu, inc, off);
        if (lane >= off) inc += n;
    }
    if (lane == 31) wsum[wid] = inc;
    __syncthreads();
    if (wid == 0) {
        int s = wsum[lane];
        int si = s;
#pragma unroll
        for (int off = 1; off < 32; off <<= 1) {
            int n = __shfl_up_sync(0xFFFFFFFFu, si, off);
            if (lane >= off) si += n;
        }
        wsum[lane] = si - s;  // exclusive warp offsets
    }
    __syncthreads();
    int excl = inc - v + wsum[wid];
    if (i <= NN) g_rowptr[i] = excl;
    if (tid == SCAN_B - 1) g_bsum[blockIdx.x] = excl + v;
}

__global__ void __launch_bounds__(256) scan3_kernel() {
    __shared__ int s_off;
    int tid = threadIdx.x;
    int i = blockIdx.x * 256 + tid;
    int blk = blockIdx.x >> 2;  // 1024 = 4*256: all i in this block share one scan-block
    if (tid < 32) {
        int a = (tid < blk) ? g_bsum[tid] : 0;
        if (tid + 32 < blk) a += g_bsum[tid + 32];
#pragma unroll
        for (int off = 16; off; off >>= 1) a += __shfl_down_sync(0xFFFFFFFFu, a, off);
        if (tid == 0) s_off = a;
    }
    __syncthreads();
    if (i <= NN) {
        int rp = g_rowptr[i] + s_off;
        g_rowptr[i] = rp;
        if (i < NN) {
            g_cnt[i]  = rp;
            g_dinv[i] = rsqrtf((float)(g_deg[i] + 1));  // +1: self loop
        }
    }
}

__global__ void fill_kernel(const int* __restrict__ src, const int* __restrict__ dst) {
    int i = blockIdx.x * blockDim.x + threadIdx.x;
    if (i < NE) {
        int slot = atomicAdd(&g_cnt[dst[i]], 1);
        g_csr[slot] = src[i];
    }
}

// ---------------- GEMM-1: g_hb = bf16(x @ W1) ----------------
// R4-proven config: 128x128 tile, 256 threads, 8x8/thread, f32x2 mainloop.
__global__ void __launch_bounds__(256) gemm_kernel(const float* __restrict__ A,
                                                   const float* __restrict__ W) {
    __shared__ float As[16][132];
    __shared__ float Bs[16][128];

    int tid = threadIdx.x;
    int tx = tid & 15;
    int ty = tid >> 4;
    int rowBase = blockIdx.x * 128;

    unsigned long long acc2[8][4];
#pragma unroll
    for (int i = 0; i < 8; i++)
#pragma unroll
        for (int j = 0; j < 4; j++) acc2[i][j] = 0ull;

    for (int kt = 0; kt < 128; kt += 16) {
#pragma unroll
        for (int l = 0; l < 2; l++) {
            int idx = tid + l * 256;
            int r   = idx >> 2;
            int k4  = (idx & 3) << 2;
            float4 v = make_float4(0.f, 0.f, 0.f, 0.f);
            int gr = rowBase + r;
            if (gr < NN) v = *(const float4*)(A + gr * 128 + kt + k4);
            As[k4 + 0][r] = v.x;
            As[k4 + 1][r] = v.y;
            As[k4 + 2][r] = v.z;
            As[k4 + 3][r] = v.w;
        }
#pragma unroll
        for (int l = 0; l < 2; l++) {
            int idx = tid + l * 256;
            int kk  = idx >> 5;
            int n4  = (idx & 31) << 2;
            *(float4*)&Bs[kk][n4] = *(const float4*)(W + (kt + kk) * 128 + n4);
        }
        __syncthreads();

#pragma unroll
        for (int k = 0; k < 16; k++) {
            float4 a0 = *(const float4*)&As[k][ty * 8];
            float4 a1 = *(const float4*)&As[k][ty * 8 + 4];
            unsigned long long ad[8];
            ad[0] = pack2(a0.x, a0.x); ad[1] = pack2(a0.y, a0.y);
            ad[2] = pack2(a0.z, a0.z); ad[3] = pack2(a0.w, a0.w);
            ad[4] = pack2(a1.x, a1.x); ad[5] = pack2(a1.y, a1.y);
            ad[6] = pack2(a1.z, a1.z); ad[7] = pack2(a1.w, a1.w);
            ulonglong2 bp0 = *(const ulonglong2*)&Bs[k][tx * 4];
            ulonglong2 bp1 = *(const ulonglong2*)&Bs[k][tx * 4 + 64];
            unsigned long long bd[4] = {bp0.x, bp0.y, bp1.x, bp1.y};
#pragma unroll
            for (int i = 0; i < 8; i++)
#pragma unroll
                for (int j = 0; j < 4; j++)
                    acc2[i][j] = fma2(ad[i], bd[j], acc2[i][j]);
        }
        __syncthreads();
    }

    // epilogue: convert to bf16, store
#pragma unroll
    for (int i = 0; i < 8; i++) {
        int gr = rowBase + ty * 8 + i;
        if (gr < NN) {
            float o[8];
#pragma unroll
            for (int j = 0; j < 4; j++) {
                float lo, hi;
                unpack2(acc2[i][j], lo, hi);
                o[2 * j]     = lo;
                o[2 * j + 1] = hi;
            }
            uint2 p0 = f4_to_bf4(make_float4(o[0], o[1], o[2], o[3]));
            uint2 p1 = f4_to_bf4(make_float4(o[4], o[5], o[6], o[7]));
            *(uint2*)(g_hb + gr * 128 + tx * 4)      = p0;
            *(uint2*)(g_hb + gr * 128 + tx * 4 + 64) = p1;
        }
    }
}

// ---------------- aggregation: warp per node, bf16 gathers ----------------
// LAYER==1: in = g_hb (unscaled h1). x2 = relu(dinv_i*(dinv_i*h_i + sum dinv_j*h_j) + b1),
//           stores bf16(dinv_i * x2) into g_x2b.
// LAYER==2: in = g_x2b (pre-scaled). y_i = dinv_i*(x2s_i + sum x2s_j);
//           REDG-accumulates y_i into g_zsum[batch[i]] (pool fused, no bias).
template <int LAYER>
__global__ void __launch_bounds__(256) agg_kernel(const float* __restrict__ bias,
                                                  const int* __restrict__ batch) {
    int w    = (blockIdx.x * blockDim.x + threadIdx.x) >> 5;
    int lane = threadIdx.x & 31;
    if (w >= NN) return;

    int beg = g_rowptr[w];
    int end = g_rowptr[w + 1];
    float dv = g_dinv[w];

    const uint2* hv = (LAYER == 1) ? (const uint2*)g_hb : (const uint2*)g_x2b;
    float4 self = bf4_to_f4(hv[w * 32 + lane]);
    float4 acc;
    if (LAYER == 1) {
        acc = make_float4(self.x * dv, self.y * dv, self.z * dv, self.w * dv);
    } else {
        acc = self;
    }

    int k = beg;
    for (; k + 3 < end; k += 4) {
        int s0 = g_csr[k];
        int s1 = g_csr[k + 1];
        int s2 = g_csr[k + 2];
        int s3 = g_csr[k + 3];
        float4 v0 = bf4_to_f4(hv[s0 * 32 + lane]);
        float4 v1 = bf4_to_f4(hv[s1 * 32 + lane]);
        float4 v2 = bf4_to_f4(hv[s2 * 32 + lane]);
        float4 v3 = bf4_to_f4(hv[s3 * 32 + lane]);
        if (LAYER == 1) {
            float d0 = __ldg(&g_dinv[s0]);
            float d1 = __ldg(&g_dinv[s1]);
            float d2 = __ldg(&g_dinv[s2]);
            float d3 = __ldg(&g_dinv[s3]);
            acc.x = fmaf(v0.x, d0, acc.x); acc.y = fmaf(v0.y, d0, acc.y);
            acc.z = fmaf(v0.z, d0, acc.z); acc.w = fmaf(v0.w, d0, acc.w);
            acc.x = fmaf(v1.x, d1, acc.x); acc.y = fmaf(v1.y, d1, acc.y);
            acc.z = fmaf(v1.z, d1, acc.z); acc.w = fmaf(v1.w, d1, acc.w);
            acc.x = fmaf(v2.x, d2, acc.x); acc.y = fmaf(v2.y, d2, acc.y);
            acc.z = fmaf(v2.z, d2, acc.z); acc.w = fmaf(v2.w, d2, acc.w);
            acc.x = fmaf(v3.x, d3, acc.x); acc.y = fmaf(v3.y, d3, acc.y);
            acc.z = fmaf(v3.z, d3, acc.z); acc.w = fmaf(v3.w, d3, acc.w);
        } else {
            acc.x += v0.x + v1.x + v2.x + v3.x;
            acc.y += v0.y + v1.y + v2.y + v3.y;
            acc.z += v0.z + v1.z + v2.z + v3.z;
            acc.w += v0.w + v1.w + v2.w + v3.w;
        }
    }
    for (; k < end; k++) {
        int s = g_csr[k];
        float4 v = bf4_to_f4(hv[s * 32 + lane]);
        if (LAYER == 1) {
            float d = __ldg(&g_dinv[s]);
            acc.x = fmaf(v.x, d, acc.x); acc.y = fmaf(v.y, d, acc.y);
            acc.z = fmaf(v.z, d, acc.z); acc.w = fmaf(v.w, d, acc.w);
        } else {
            acc.x += v.x; acc.y += v.y; acc.z += v.z; acc.w += v.w;
        }
    }

    if (LAYER == 1) {
        float4 bb = ((const float4*)bias)[lane];
        float4 r;
        r.x = fmaf(dv, acc.x, bb.x);
        r.y = fmaf(dv, acc.y, bb.y);
        r.z = fmaf(dv, acc.z, bb.z);
        r.w = fmaf(dv, acc.w, bb.w);
        // relu then pre-scale by dinv_i for the next aggregation
        r.x = fmaxf(r.x, 0.f) * dv;
        r.y = fmaxf(r.y, 0.f) * dv;
        r.z = fmaxf(r.z, 0.f) * dv;
        r.w = fmaxf(r.w, 0.f) * dv;
        ((uint2*)g_x2b)[w * 32 + lane] = f4_to_bf4(r);
    } else {
        int g = batch[w];
        float* zs = g_zsum + g * 128 + lane * 4;
        atomicAdd(zs + 0, dv * acc.x);   // no return use -> REDG
        atomicAdd(zs + 1, dv * acc.y);
        atomicAdd(zs + 2, dv * acc.z);
        atomicAdd(zs + 3, dv * acc.w);
    }
}

// ---------------- final: out = (zsum / count) @ W2 + b2  (64x128x128) ----------------
__device__ __forceinline__ int lower_bound_dev(const int* a, int n, int key) {
    int lo = 0, hi = n;
    while (lo < hi) {
        int mid = (lo + hi) >> 1;
        if (a[mid] < key) lo = mid + 1; else hi = mid;
    }
    return lo;
}

__global__ void __launch_bounds__(128) out_gemm_kernel(const int* __restrict__ batch,
                                                       const float* __restrict__ W2,
                                                       const float* __restrict__ b2,
                                                       float* __restrict__ out) {
    __shared__ float zrow[128];
    __shared__ int s_cnt;
    int g = blockIdx.x;
    int f = threadIdx.x;
    if (f == 0) {
        int lo = lower_bound_dev(batch, NN, g);
        int hi = lower_bound_dev(batch, NN, g + 1);
        s_cnt = hi - lo;
    }
    __syncthreads();
    int cnt = s_cnt;
    zrow[f] = g_zsum[g * 128 + f] / fmaxf((float)cnt, 1.0f);
    __syncthreads();
    if (cnt == 0) {          // empty graph: reference yields exactly 0
        out[g * 128 + f] = 0.0f;
        return;
    }
    float acc = b2[f];
#pragma unroll 8
    for (int k = 0; k < 128; k++) acc = fmaf(zrow[k], W2[k * 128 + f], acc);
    out[g * 128 + f] = acc;
}

// ---------------- launch ----------------
extern "C" void kernel_launch(void* const* d_in, const int* in_sizes, int n_in,
                              void* d_out, int out_size) {
    const float* x     = (const float*)d_in[0];
    const int*   ei    = (const int*)d_in[1];   // [2, E] row-major
    const int*   batch = (const int*)d_in[2];
    const float* W1    = (const float*)d_in[3];
    const float* b1    = (const float*)d_in[4];
    const float* W2    = (const float*)d_in[5];
    const float* b2    = (const float*)d_in[6];
    float* out = (float*)d_out;

    const int* src = ei;        // edge_index[0]
    const int* dst = ei + NE;   // edge_index[1]

    // One-time host resources (streams/events are not device memory).
    static cudaStream_t s2 = nullptr;
    static cudaEvent_t evFork = nullptr, evJoin = nullptr;
    static void* degPtr = nullptr;
    static void* zsumPtr = nullptr;
    if (s2 == nullptr) {
        cudaStreamCreateWithFlags(&s2, cudaStreamNonBlocking);
        cudaEventCreateWithFlags(&evFork, cudaEventDisableTiming);
        cudaEventCreateWithFlags(&evJoin, cudaEventDisableTiming);
        cudaGetSymbolAddress(&degPtr, g_deg);
        cudaGetSymbolAddress(&zsumPtr, g_zsum);
    }

    // Fork: GEMM-1 (no dependence on edges/dinv) runs on s2 while the CSR
    // build runs on the main stream.
    cudaEventRecord(evFork, 0);
    cudaStreamWaitEvent(s2, evFork, 0);
    gemm_kernel<<<(NN + 127) / 128, 256, 0, s2>>>(x, W1);
    cudaEventRecord(evJoin, s2);

    // CSR build (by destination) + dinv, on main stream
    cudaMemsetAsync(degPtr, 0, NN * sizeof(int), 0);
    cudaMemsetAsync(zsumPtr, 0, NG * DD * sizeof(float), 0);
    hist_kernel<<<(NE + 255) / 256, 256>>>(dst);
    scan1_kernel<<<NSCAN, SCAN_B>>>();
    scan3_kernel<<<(NN + 1 + 255) / 256, 256>>>();
    fill_kernel<<<(NE + 255) / 256, 256>>>(src, dst);

    // Join: aggregation needs both GEMM-1 output and the CSR.
    cudaStreamWaitEvent(0, evJoin, 0);

    // Layer 1 aggregation (+relu, +b1), writes dinv-prescaled bf16 x2 to g_x2b.
    agg_kernel<1><<<(NN + 7) / 8, 256>>>(b1, nullptr);

    // Layer 2 aggregation fused with pooling (REDG into g_zsum).
    agg_kernel<2><<<(NN + 7) / 8, 256>>>(nullptr, batch);

    // out = (zsum/count) @ W2 + b2
    out_gemm_kernel<<<NG, DD>>>(batch, W2, b2, out);
}

// round 9
// speedup vs baseline: 1.6691x; 1.6691x over previous
#include <cuda_runtime.h>
#include <cuda_bf16.h>

// Problem constants (fixed by the reference)
constexpr int NN = 40000;   // nodes
constexpr int NE = 640000;  // edges
constexpr int DD = 128;     // feature dim
constexpr int NG = 64;      // graphs

constexpr int SCAN_B = 1024;
constexpr int NSCAN  = (NN + SCAN_B) / SCAN_B;  // 40 blocks

// ---------------- scratch (static device globals; no allocations) ----------------
__device__ __nv_bfloat16 g_hb [NN * DD];  // gemm1 out (unscaled, bf16)
__device__ __nv_bfloat16 g_x2b[NN * DD];  // agg1 out (dinv-prescaled relu, bf16)
__device__ float g_y  [NN * DD];          // agg2 out (fp32)
__device__ float g_z  [NG * DD];          // pooled per-graph means
__device__ int   g_deg[NN];               // in-degree (without self loop)
__device__ float g_dinv[NN];              // 1/sqrt(deg+1)
__device__ int   g_rowptr[NN + 1];        // CSR row pointers (by dst)
__device__ int   g_cnt[NN];               // fill cursors
__device__ int   g_csr[NE];               // CSR column indices (src node per edge)
__device__ int   g_bsum[64];              // scan block sums (NSCAN=40 used)

// ---------------- packed f32x2 helpers ----------------
__device__ __forceinline__ unsigned long long pack2(float lo, float hi) {
    unsigned long long r;
    asm("mov.b64 %0, {%1, %2};" : "=l"(r) : "f"(lo), "f"(hi));
    return r;
}
__device__ __forceinline__ void unpack2(unsigned long long v, float& lo, float& hi) {
    asm("mov.b64 {%0, %1}, %2;" : "=f"(lo), "=f"(hi) : "l"(v));
}
__device__ __forceinline__ unsigned long long fma2(unsigned long long a,
                                                   unsigned long long b,
                                                   unsigned long long c) {
    unsigned long long d;
    asm("fma.rn.f32x2 %0, %1, %2, %3;" : "=l"(d) : "l"(a), "l"(b), "l"(c));
    return d;
}

// ---------------- bf16x4 helpers ----------------
__device__ __forceinline__ float4 bf4_to_f4(uint2 p) {
    __nv_bfloat162 a = *reinterpret_cast<__nv_bfloat162*>(&p.x);
    __nv_bfloat162 b = *reinterpret_cast<__nv_bfloat162*>(&p.y);
    float2 f0 = __bfloat1622float2(a);
    float2 f1 = __bfloat1622float2(b);
    return make_float4(f0.x, f0.y, f1.x, f1.y);
}
__device__ __forceinline__ uint2 f4_to_bf4(float4 v) {
    __nv_bfloat162 a = __float22bfloat162_rn(make_float2(v.x, v.y));
    __nv_bfloat162 b = __float22bfloat162_rn(make_float2(v.z, v.w));
    uint2 r;
    r.x = *reinterpret_cast<unsigned*>(&a);
    r.y = *reinterpret_cast<unsigned*>(&b);
    return r;
}

// ---------------- CSR construction ----------------
__global__ void hist_kernel(const int* __restrict__ dst) {
    int i = blockIdx.x * blockDim.x + threadIdx.x;
    if (i < NE) atomicAdd(&g_deg[dst[i]], 1);
}

__global__ void __launch_bounds__(SCAN_B) scan1_kernel() {
    __shared__ int wsum[32];
    int tid = threadIdx.x, lane = tid & 31, wid = tid >> 5;
    int i = blockIdx.x * SCAN_B + tid;
    int v = (i < NN) ? g_deg[i] : 0;
    int inc = v;
#pragma unroll
    for (int off = 1; off < 32; off <<= 1) {
        int n = __shfl_up_sync(0xFFFFFFFFu, inc, off);
        if (lane >= off) inc += n;
    }
    if (lane == 31) wsum[wid] = inc;
    __syncthreads();
    if (wid == 0) {
        int s = wsum[lane];
        int si = s;
#pragma unroll
        for (int off = 1; off < 32; off <<= 1) {
            int n = __shfl_up_sync(0xFFFFFFFFu, si, off);
            if (lane >= off) si += n;
        }
        wsum[lane] = si - s;  // exclusive warp offsets
    }
    __syncthreads();
    int excl = inc - v + wsum[wid];
    if (i <= NN) g_rowptr[i] = excl;
    if (tid == SCAN_B - 1) g_bsum[blockIdx.x] = excl + v;
}

__global__ void __launch_bounds__(256) scan3_kernel() {
    __shared__ int s_off;
    int tid = threadIdx.x;
    int i = blockIdx.x * 256 + tid;
    int blk = blockIdx.x >> 2;  // 1024 = 4*256: all i in this block share one scan-block
    if (tid < 32) {
        int a = (tid < blk) ? g_bsum[tid] : 0;
        if (tid + 32 < blk) a += g_bsum[tid + 32];
#pragma unroll
        for (int off = 16; off; off >>= 1) a += __shfl_down_sync(0xFFFFFFFFu, a, off);
        if (tid == 0) s_off = a;
    }
    __syncthreads();
    if (i <= NN) {
        int rp = g_rowptr[i] + s_off;
        g_rowptr[i] = rp;
        if (i < NN) {
            g_cnt[i]  = rp;
            g_dinv[i] = rsqrtf((float)(g_deg[i] + 1));  // +1: self loop
        }
    }
}

__global__ void fill_kernel(const int* __restrict__ src, const int* __restrict__ dst) {
    int i = blockIdx.x * blockDim.x + threadIdx.x;
    if (i < NE) {
        int slot = atomicAdd(&g_cnt[dst[i]], 1);
        g_csr[slot] = src[i];
    }
}

// ---------------- GEMM-1: g_hb = bf16(x @ W1) ----------------
// R4-proven config: 128x128 tile, 256 threads, 8x8/thread, f32x2 mainloop.
__global__ void __launch_bounds__(256) gemm_kernel(const float* __restrict__ A,
                                                   const float* __restrict__ W) {
    __shared__ float As[16][132];
    __shared__ float Bs[16][128];

    int tid = threadIdx.x;
    int tx = tid & 15;
    int ty = tid >> 4;
    int rowBase = blockIdx.x * 128;

    unsigned long long acc2[8][4];
#pragma unroll
    for (int i = 0; i < 8; i++)
#pragma unroll
        for (int j = 0; j < 4; j++) acc2[i][j] = 0ull;

    for (int kt = 0; kt < 128; kt += 16) {
#pragma unroll
        for (int l = 0; l < 2; l++) {
            int idx = tid + l * 256;
            int r   = idx >> 2;
            int k4  = (idx & 3) << 2;
            float4 v = make_float4(0.f, 0.f, 0.f, 0.f);
            int gr = rowBase + r;
            if (gr < NN) v = *(const float4*)(A + gr * 128 + kt + k4);
            As[k4 + 0][r] = v.x;
            As[k4 + 1][r] = v.y;
            As[k4 + 2][r] = v.z;
            As[k4 + 3][r] = v.w;
        }
#pragma unroll
        for (int l = 0; l < 2; l++) {
            int idx = tid + l * 256;
            int kk  = idx >> 5;
            int n4  = (idx & 31) << 2;
            *(float4*)&Bs[kk][n4] = *(const float4*)(W + (kt + kk) * 128 + n4);
        }
        __syncthreads();

#pragma unroll
        for (int k = 0; k < 16; k++) {
            float4 a0 = *(const float4*)&As[k][ty * 8];
            float4 a1 = *(const float4*)&As[k][ty * 8 + 4];
            unsigned long long ad[8];
            ad[0] = pack2(a0.x, a0.x); ad[1] = pack2(a0.y, a0.y);
            ad[2] = pack2(a0.z, a0.z); ad[3] = pack2(a0.w, a0.w);
            ad[4] = pack2(a1.x, a1.x); ad[5] = pack2(a1.y, a1.y);
            ad[6] = pack2(a1.z, a1.z); ad[7] = pack2(a1.w, a1.w);
            ulonglong2 bp0 = *(const ulonglong2*)&Bs[k][tx * 4];
            ulonglong2 bp1 = *(const ulonglong2*)&Bs[k][tx * 4 + 64];
            unsigned long long bd[4] = {bp0.x, bp0.y, bp1.x, bp1.y};
#pragma unroll
            for (int i = 0; i < 8; i++)
#pragma unroll
                for (int j = 0; j < 4; j++)
                    acc2[i][j] = fma2(ad[i], bd[j], acc2[i][j]);
        }
        __syncthreads();
    }

    // epilogue: convert to bf16, store
#pragma unroll
    for (int i = 0; i < 8; i++) {
        int gr = rowBase + ty * 8 + i;
        if (gr < NN) {
            float o[8];
#pragma unroll
            for (int j = 0; j < 4; j++) {
                float lo, hi;
                unpack2(acc2[i][j], lo, hi);
                o[2 * j]     = lo;
                o[2 * j + 1] = hi;
            }
            uint2 p0 = f4_to_bf4(make_float4(o[0], o[1], o[2], o[3]));
            uint2 p1 = f4_to_bf4(make_float4(o[4], o[5], o[6], o[7]));
            *(uint2*)(g_hb + gr * 128 + tx * 4)      = p0;
            *(uint2*)(g_hb + gr * 128 + tx * 4 + 64) = p1;
        }
    }
}

// ---------------- aggregation: warp per node, bf16 gathers ----------------
// LAYER==1: in = g_hb (unscaled h1). x2 = relu(dinv_i*(dinv_i*h_i + sum dinv_j*h_j) + b1),
//           stores bf16(dinv_i * x2) into g_x2b.
// LAYER==2: in = g_x2b (pre-scaled). y_i = dinv_i*(x2s_i + sum x2s_j) -> g_y (fp32).
template <int LAYER>
__global__ void __launch_bounds__(256) agg_kernel(const float* __restrict__ bias) {
    int w    = (blockIdx.x * blockDim.x + threadIdx.x) >> 5;
    int lane = threadIdx.x & 31;
    if (w >= NN) return;

    int beg = g_rowptr[w];
    int end = g_rowptr[w + 1];
    float dv = g_dinv[w];

    const uint2* hv = (LAYER == 1) ? (const uint2*)g_hb : (const uint2*)g_x2b;
    float4 self = bf4_to_f4(hv[w * 32 + lane]);
    float4 acc;
    if (LAYER == 1) {
        acc = make_float4(self.x * dv, self.y * dv, self.z * dv, self.w * dv);
    } else {
        acc = self;
    }

    int k = beg;
    for (; k + 3 < end; k += 4) {
        int s0 = g_csr[k];
        int s1 = g_csr[k + 1];
        int s2 = g_csr[k + 2];
        int s3 = g_csr[k + 3];
        float4 v0 = bf4_to_f4(hv[s0 * 32 + lane]);
        float4 v1 = bf4_to_f4(hv[s1 * 32 + lane]);
        float4 v2 = bf4_to_f4(hv[s2 * 32 + lane]);
        float4 v3 = bf4_to_f4(hv[s3 * 32 + lane]);
        if (LAYER == 1) {
            float d0 = __ldg(&g_dinv[s0]);
            float d1 = __ldg(&g_dinv[s1]);
            float d2 = __ldg(&g_dinv[s2]);
            float d3 = __ldg(&g_dinv[s3]);
            acc.x = fmaf(v0.x, d0, acc.x); acc.y = fmaf(v0.y, d0, acc.y);
            acc.z = fmaf(v0.z, d0, acc.z); acc.w = fmaf(v0.w, d0, acc.w);
            acc.x = fmaf(v1.x, d1, acc.x); acc.y = fmaf(v1.y, d1, acc.y);
            acc.z = fmaf(v1.z, d1, acc.z); acc.w = fmaf(v1.w, d1, acc.w);
            acc.x = fmaf(v2.x, d2, acc.x); acc.y = fmaf(v2.y, d2, acc.y);
            acc.z = fmaf(v2.z, d2, acc.z); acc.w = fmaf(v2.w, d2, acc.w);
            acc.x = fmaf(v3.x, d3, acc.x); acc.y = fmaf(v3.y, d3, acc.y);
            acc.z = fmaf(v3.z, d3, acc.z); acc.w = fmaf(v3.w, d3, acc.w);
        } else {
            acc.x += v0.x + v1.x + v2.x + v3.x;
            acc.y += v0.y + v1.y + v2.y + v3.y;
            acc.z += v0.z + v1.z + v2.z + v3.z;
            acc.w += v0.w + v1.w + v2.w + v3.w;
        }
    }
    for (; k < end; k++) {
        int s = g_csr[k];
        float4 v = bf4_to_f4(hv[s * 32 + lane]);
        if (LAYER == 1) {
            float d = __ldg(&g_dinv[s]);
            acc.x = fmaf(v.x, d, acc.x); acc.y = fmaf(v.y, d, acc.y);
            acc.z = fmaf(v.z, d, acc.z); acc.w = fmaf(v.w, d, acc.w);
        } else {
            acc.x += v.x; acc.y += v.y; acc.z += v.z; acc.w += v.w;
        }
    }

    if (LAYER == 1) {
        float4 bb = ((const float4*)bias)[lane];
        float4 r;
        r.x = fmaf(dv, acc.x, bb.x);
        r.y = fmaf(dv, acc.y, bb.y);
        r.z = fmaf(dv, acc.z, bb.z);
        r.w = fmaf(dv, acc.w, bb.w);
        // relu then pre-scale by dinv_i for the next aggregation
        r.x = fmaxf(r.x, 0.f) * dv;
        r.y = fmaxf(r.y, 0.f) * dv;
        r.z = fmaxf(r.z, 0.f) * dv;
        r.w = fmaxf(r.w, 0.f) * dv;
        ((uint2*)g_x2b)[w * 32 + lane] = f4_to_bf4(r);
    } else {
        float4 r = make_float4(dv * acc.x, dv * acc.y, dv * acc.z, dv * acc.w);
        ((float4*)g_y)[w * 32 + lane] = r;
    }
}

// ---------------- pooling: one block per graph, 512 threads ----------------
__device__ __forceinline__ int lower_bound_dev(const int* a, int n, int key) {
    int lo = 0, hi = n;
    while (lo < hi) {
        int mid = (lo + hi) >> 1;
        if (a[mid] < key) lo = mid + 1; else hi = mid;
    }
    return lo;
}

__global__ void __launch_bounds__(512) pool_kernel(const int* __restrict__ batch) {
    __shared__ int s_lo, s_hi;
    __shared__ float red[4][128];
    int g = blockIdx.x;
    int t = threadIdx.x;
    int f   = t & 127;   // feature
    int seg = t >> 7;    // row slice 0..3
    if (t == 0) {
        s_lo = lower_bound_dev(batch, NN, g);
        s_hi = lower_bound_dev(batch, NN, g + 1);
    }
    __syncthreads();
    int lo = s_lo, hi = s_hi;
    float sum = 0.f;
    for (int r = lo + seg; r < hi; r += 4) sum += g_y[r * 128 + f];
    red[seg][f] = sum;
    __syncthreads();
    if (seg == 0) {
        float c = (float)(hi - lo);
        float tot = red[0][f] + red[1][f] + red[2][f] + red[3][f];
        // signal empty graph via count in g_z? store mean; empty handled in out_gemm
        g_z[g * 128 + f] = tot / fmaxf(c, 1.0f);
    }
}

// ---------------- final micro-GEMM: out = z @ W2 + b2  (64x128x128) ----------------
__global__ void __launch_bounds__(128) out_gemm_kernel(const int* __restrict__ batch,
                                                       const float* __restrict__ W2,
                                                       const float* __restrict__ b2,
                                                       float* __restrict__ out) {
    __shared__ float zrow[128];
    __shared__ int s_cnt;
    int g = blockIdx.x;
    int f = threadIdx.x;
    if (f == 0) {
        int lo = lower_bound_dev(batch, NN, g);
        int hi = lower_bound_dev(batch, NN, g + 1);
        s_cnt = hi - lo;
    }
    __syncthreads();
    zrow[f] = g_z[g * 128 + f];
    __syncthreads();
    if (s_cnt == 0) {        // empty graph: reference (pool is last op) yields 0
        out[g * 128 + f] = 0.0f;
        return;
    }
    float acc = b2[f];
#pragma unroll 8
    for (int k = 0; k < 128; k++) acc = fmaf(zrow[k], W2[k * 128 + f], acc);
    out[g * 128 + f] = acc;
}

// ---------------- launch ----------------
extern "C" void kernel_launch(void* const* d_in, const int* in_sizes, int n_in,
                              void* d_out, int out_size) {
    const float* x     = (const float*)d_in[0];
    const int*   ei    = (const int*)d_in[1];   // [2, E] row-major
    const int*   batch = (const int*)d_in[2];
    const float* W1    = (const float*)d_in[3];
    const float* b1    = (const float*)d_in[4];
    const float* W2    = (const float*)d_in[5];
    const float* b2    = (const float*)d_in[6];
    float* out = (float*)d_out;

    const int* src = ei;        // edge_index[0]
    const int* dst = ei + NE;   // edge_index[1]

    // One-time host resources (streams/events are not device memory).
    static cudaStream_t s2 = nullptr;
    static cudaEvent_t evFork = nullptr, evJoin = nullptr;
    static void* degPtr = nullptr;
    if (s2 == nullptr) {
        cudaStreamCreateWithFlags(&s2, cudaStreamNonBlocking);
        cudaEventCreateWithFlags(&evFork, cudaEventDisableTiming);
        cudaEventCreateWithFlags(&evJoin, cudaEventDisableTiming);
        cudaGetSymbolAddress(&degPtr, g_deg);
    }

    // Fork: GEMM-1 (no dependence on edges/dinv) runs on s2 while the CSR
    // build runs on the main stream.
    cudaEventRecord(evFork, 0);
    cudaStreamWaitEvent(s2, evFork, 0);
    gemm_kernel<<<(NN + 127) / 128, 256, 0, s2>>>(x, W1);
    cudaEventRecord(evJoin, s2);

    // CSR build (by destination) + dinv, on main stream
    cudaMemsetAsync(degPtr, 0, NN * sizeof(int), 0);
    hist_kernel<<<(NE + 255) / 256, 256>>>(dst);
    scan1_kernel<<<NSCAN, SCAN_B>>>();
    scan3_kernel<<<(NN + 1 + 255) / 256, 256>>>();
    fill_kernel<<<(NE + 255) / 256, 256>>>(src, dst);

    // Join: aggregation needs both GEMM-1 output and the CSR.
    cudaStreamWaitEvent(0, evJoin, 0);

    // Layer 1 aggregation (+relu, +b1), writes dinv-prescaled bf16 x2 to g_x2b.
    agg_kernel<1><<<(NN + 7) / 8, 256>>>(b1);

    // Layer 2 aggregation only (W2 commuted past S and pooling), writes g_y fp32.
    agg_kernel<2><<<(NN + 7) / 8, 256>>>(nullptr);

    // Global mean pool -> z[64,128]
    pool_kernel<<<NG, 512>>>(batch);

    // out = z @ W2 + b2 (empty graphs -> 0)
    out_gemm_kernel<<<NG, DD>>>(batch, W2, b2, out);
}

// round 10
// speedup vs baseline: 1.8428x; 1.1041x over previous
#include <cuda_runtime.h>
#include <cuda_bf16.h>

// Problem constants (fixed by the reference)
constexpr int NN = 40000;   // nodes
constexpr int NE = 640000;  // edges
constexpr int DD = 128;     // feature dim
constexpr int NG = 64;      // graphs

constexpr int SCAN_B = 1024;
constexpr int NSCAN  = (NN + SCAN_B) / SCAN_B;  // 40 blocks, block 39 covers i=NN

// ---------------- scratch (static device globals; no allocations) ----------------
__device__ __nv_bfloat16 g_hb [NN * DD];  // gemm1 out (unscaled, bf16)
__device__ __nv_bfloat16 g_x2b[NN * DD];  // agg1 out (dinv-prescaled relu, bf16)
__device__ float g_y  [NN * DD];          // agg2 out (fp32)
__device__ int   g_deg[NN];               // in-degree (zeroed by agg1 for next replay)
__device__ float g_dinv[NN];              // 1/sqrt(deg+1)
__device__ int   g_rowptr[NN + 1];        // CSR row pointers (by dst)
__device__ int   g_cnt[NN];               // fill cursors
__device__ int   g_csr[NE];               // CSR column indices (src node per edge)
__device__ int   g_bsum[64];              // scan block aggregates
__device__ int   g_flagv[64];             // scan lookback flags (zeroed by agg1)

// ---------------- packed f32x2 helpers ----------------
__device__ __forceinline__ unsigned long long pack2(float lo, float hi) {
    unsigned long long r;
    asm("mov.b64 %0, {%1, %2};" : "=l"(r) : "f"(lo), "f"(hi));
    return r;
}
__device__ __forceinline__ void unpack2(unsigned long long v, float& lo, float& hi) {
    asm("mov.b64 {%0, %1}, %2;" : "=f"(lo), "=f"(hi) : "l"(v));
}
__device__ __forceinline__ unsigned long long fma2(unsigned long long a,
                                                   unsigned long long b,
                                                   unsigned long long c) {
    unsigned long long d;
    asm("fma.rn.f32x2 %0, %1, %2, %3;" : "=l"(d) : "l"(a), "l"(b), "l"(c));
    return d;
}

// ---------------- bf16x4 helpers ----------------
__device__ __forceinline__ float4 bf4_to_f4(uint2 p) {
    __nv_bfloat162 a = *reinterpret_cast<__nv_bfloat162*>(&p.x);
    __nv_bfloat162 b = *reinterpret_cast<__nv_bfloat162*>(&p.y);
    float2 f0 = __bfloat1622float2(a);
    float2 f1 = __bfloat1622float2(b);
    return make_float4(f0.x, f0.y, f1.x, f1.y);
}
__device__ __forceinline__ uint2 f4_to_bf4(float4 v) {
    __nv_bfloat162 a = __float22bfloat162_rn(make_float2(v.x, v.y));
    __nv_bfloat162 b = __float22bfloat162_rn(make_float2(v.z, v.w));
    uint2 r;
    r.x = *reinterpret_cast<unsigned*>(&a);
    r.y = *reinterpret_cast<unsigned*>(&b);
    return r;
}

// ---------------- CSR construction ----------------
__global__ void hist_kernel(const int* __restrict__ dst) {
    int i = blockIdx.x * blockDim.x + threadIdx.x;
    if (i < NE) atomicAdd(&g_deg[dst[i]], 1);
}

// Single-pass scan with decoupled lookback (40 blocks, all co-resident in
// wave 1 so cross-block spinning is safe). Replaces scan1+scan3. Writes
// rowptr, fill cursors, dinv. Flags/bsum zeroed by previous replay's agg1.
__global__ void __launch_bounds__(SCAN_B) scan_kernel() {
    __shared__ int wsum[32];
    __shared__ int s_off;
    int tid = threadIdx.x, lane = tid & 31, wid = tid >> 5;
    int b = blockIdx.x;
    int i = b * SCAN_B + tid;
    int v = (i < NN) ? g_deg[i] : 0;
    int inc = v;
#pragma unroll
    for (int off = 1; off < 32; off <<= 1) {
        int n = __shfl_up_sync(0xFFFFFFFFu, inc, off);
        if (lane >= off) inc += n;
    }
    if (lane == 31) wsum[wid] = inc;
    __syncthreads();
    if (wid == 0) {
        // scan the 32 warp sums; publish block aggregate ASAP
        int s = wsum[lane];
        int si = s;
#pragma unroll
        for (int off = 1; off < 32; off <<= 1) {
            int n = __shfl_up_sync(0xFFFFFFFFu, si, off);
            if (lane >= off) si += n;
        }
        int total = __shfl_sync(0xFFFFFFFFu, si, 31);
        if (lane == 0) {
            g_bsum[b] = total;
            __threadfence();
            *(volatile int*)&g_flagv[b] = 1;
        }
        wsum[lane] = si - s;  // exclusive warp offsets
        // lookback over predecessors
        int a = 0;
        if (b > 0) {
            bool n0 = lane < b;
            bool n1 = lane + 32 < b;
            volatile int* fl = (volatile int*)g_flagv;
            while (true) {
                int f0 = n0 ? fl[lane] : 1;
                int f1 = n1 ? fl[lane + 32] : 1;
                if (__all_sync(0xFFFFFFFFu, (f0 != 0) && (f1 != 0))) break;
            }
            __threadfence();
            a = (n0 ? g_bsum[lane] : 0) + (n1 ? g_bsum[lane + 32] : 0);
#pragma unroll
            for (int off = 16; off; off >>= 1)
                a += __shfl_down_sync(0xFFFFFFFFu, a, off);
        }
        if (lane == 0) s_off = a;
    }
    __syncthreads();
    int excl = inc - v + wsum[wid] + s_off;
    if (i <= NN) {
        g_rowptr[i] = excl;
        if (i < NN) {
            g_cnt[i]  = excl;
            g_dinv[i] = rsqrtf((float)(v + 1));  // +1: self loop
        }
    }
}

__global__ void fill_kernel(const int* __restrict__ src, const int* __restrict__ dst) {
    int i = blockIdx.x * blockDim.x + threadIdx.x;
    if (i < NE) {
        int slot = atomicAdd(&g_cnt[dst[i]], 1);
        g_csr[slot] = src[i];
    }
}

// ---------------- GEMM-1: g_hb = bf16(x @ W1) ----------------
// R4-proven config: 128x128 tile, 256 threads, 8x8/thread, f32x2 mainloop.
__global__ void __launch_bounds__(256) gemm_kernel(const float* __restrict__ A,
                                                   const float* __restrict__ W) {
    __shared__ float As[16][132];
    __shared__ float Bs[16][128];

    int tid = threadIdx.x;
    int tx = tid & 15;
    int ty = tid >> 4;
    int rowBase = blockIdx.x * 128;

    unsigned long long acc2[8][4];
#pragma unroll
    for (int i = 0; i < 8; i++)
#pragma unroll
        for (int j = 0; j < 4; j++) acc2[i][j] = 0ull;

    for (int kt = 0; kt < 128; kt += 16) {
#pragma unroll
        for (int l = 0; l < 2; l++) {
            int idx = tid + l * 256;
            int r   = idx >> 2;
            int k4  = (idx & 3) << 2;
            float4 v = make_float4(0.f, 0.f, 0.f, 0.f);
            int gr = rowBase + r;
            if (gr < NN) v = *(const float4*)(A + gr * 128 + kt + k4);
            As[k4 + 0][r] = v.x;
            As[k4 + 1][r] = v.y;
            As[k4 + 2][r] = v.z;
            As[k4 + 3][r] = v.w;
        }
#pragma unroll
        for (int l = 0; l < 2; l++) {
            int idx = tid + l * 256;
            int kk  = idx >> 5;
            int n4  = (idx & 31) << 2;
            *(float4*)&Bs[kk][n4] = *(const float4*)(W + (kt + kk) * 128 + n4);
        }
        __syncthreads();

#pragma unroll
        for (int k = 0; k < 16; k++) {
            float4 a0 = *(const float4*)&As[k][ty * 8];
            float4 a1 = *(const float4*)&As[k][ty * 8 + 4];
            unsigned long long ad[8];
            ad[0] = pack2(a0.x, a0.x); ad[1] = pack2(a0.y, a0.y);
            ad[2] = pack2(a0.z, a0.z); ad[3] = pack2(a0.w, a0.w);
            ad[4] = pack2(a1.x, a1.x); ad[5] = pack2(a1.y, a1.y);
            ad[6] = pack2(a1.z, a1.z); ad[7] = pack2(a1.w, a1.w);
            ulonglong2 bp0 = *(const ulonglong2*)&Bs[k][tx * 4];
            ulonglong2 bp1 = *(const ulonglong2*)&Bs[k][tx * 4 + 64];
            unsigned long long bd[4] = {bp0.x, bp0.y, bp1.x, bp1.y};
#pragma unroll
            for (int i = 0; i < 8; i++)
#pragma unroll
                for (int j = 0; j < 4; j++)
                    acc2[i][j] = fma2(ad[i], bd[j], acc2[i][j]);
        }
        __syncthreads();
    }

#pragma unroll
    for (int i = 0; i < 8; i++) {
        int gr = rowBase + ty * 8 + i;
        if (gr < NN) {
            float o[8];
#pragma unroll
            for (int j = 0; j < 4; j++) {
                float lo, hi;
                unpack2(acc2[i][j], lo, hi);
                o[2 * j]     = lo;
                o[2 * j + 1] = hi;
            }
            uint2 p0 = f4_to_bf4(make_float4(o[0], o[1], o[2], o[3]));
            uint2 p1 = f4_to_bf4(make_float4(o[4], o[5], o[6], o[7]));
            *(uint2*)(g_hb + gr * 128 + tx * 4)      = p0;
            *(uint2*)(g_hb + gr * 128 + tx * 4 + 64) = p1;
        }
    }
}

// ---------------- aggregation: warp per node, bf16 gathers ----------------
// LAYER==1: in = g_hb. x2 = relu(dinv_i*(dinv_i*h_i + sum dinv_j*h_j) + b1),
//           stores bf16(dinv_i * x2). Also re-zeros g_deg/g_flagv for the
//           next graph replay (their last readers have completed).
// LAYER==2: in = g_x2b (pre-scaled). y_i = dinv_i*(x2s_i + sum x2s_j) -> g_y.
template <int LAYER>
__global__ void __launch_bounds__(256) agg_kernel(const float* __restrict__ bias) {
    int t = blockIdx.x * blockDim.x + threadIdx.x;
    if (LAYER == 1) {
        // maintain zero-invariant for next replay (deg, lookback flags)
        if (t < NN) g_deg[t] = 0;
        if (t < 64) g_flagv[t] = 0;
    }
    int w    = t >> 5;
    int lane = threadIdx.x & 31;
    if (w >= NN) return;

    int beg = g_rowptr[w];
    int end = g_rowptr[w + 1];
    float dv = g_dinv[w];

    const uint2* hv = (LAYER == 1) ? (const uint2*)g_hb : (const uint2*)g_x2b;
    float4 self = bf4_to_f4(hv[w * 32 + lane]);
    float4 acc;
    if (LAYER == 1) {
        acc = make_float4(self.x * dv, self.y * dv, self.z * dv, self.w * dv);
    } else {
        acc = self;
    }

    int k = beg;
    for (; k + 3 < end; k += 4) {
        int s0 = g_csr[k];
        int s1 = g_csr[k + 1];
        int s2 = g_csr[k + 2];
        int s3 = g_csr[k + 3];
        float4 v0 = bf4_to_f4(hv[s0 * 32 + lane]);
        float4 v1 = bf4_to_f4(hv[s1 * 32 + lane]);
        float4 v2 = bf4_to_f4(hv[s2 * 32 + lane]);
        float4 v3 = bf4_to_f4(hv[s3 * 32 + lane]);
        if (LAYER == 1) {
            float d0 = __ldg(&g_dinv[s0]);
            float d1 = __ldg(&g_dinv[s1]);
            float d2 = __ldg(&g_dinv[s2]);
            float d3 = __ldg(&g_dinv[s3]);
            acc.x = fmaf(v0.x, d0, acc.x); acc.y = fmaf(v0.y, d0, acc.y);
            acc.z = fmaf(v0.z, d0, acc.z); acc.w = fmaf(v0.w, d0, acc.w);
            acc.x = fmaf(v1.x, d1, acc.x); acc.y = fmaf(v1.y, d1, acc.y);
            acc.z = fmaf(v1.z, d1, acc.z); acc.w = fmaf(v1.w, d1, acc.w);
            acc.x = fmaf(v2.x, d2, acc.x); acc.y = fmaf(v2.y, d2, acc.y);
            acc.z = fmaf(v2.z, d2, acc.z); acc.w = fmaf(v2.w, d2, acc.w);
            acc.x = fmaf(v3.x, d3, acc.x); acc.y = fmaf(v3.y, d3, acc.y);
            acc.z = fmaf(v3.z, d3, acc.z); acc.w = fmaf(v3.w, d3, acc.w);
        } else {
            acc.x += v0.x + v1.x + v2.x + v3.x;
            acc.y += v0.y + v1.y + v2.y + v3.y;
            acc.z += v0.z + v1.z + v2.z + v3.z;
            acc.w += v0.w + v1.w + v2.w + v3.w;
        }
    }
    for (; k < end; k++) {
        int s = g_csr[k];
        float4 v = bf4_to_f4(hv[s * 32 + lane]);
        if (LAYER == 1) {
            float d = __ldg(&g_dinv[s]);
            acc.x = fmaf(v.x, d, acc.x); acc.y = fmaf(v.y, d, acc.y);
            acc.z = fmaf(v.z, d, acc.z); acc.w = fmaf(v.w, d, acc.w);
        } else {
            acc.x += v.x; acc.y += v.y; acc.z += v.z; acc.w += v.w;
        }
    }

    if (LAYER == 1) {
        float4 bb = ((const float4*)bias)[lane];
        float4 r;
        r.x = fmaf(dv, acc.x, bb.x);
        r.y = fmaf(dv, acc.y, bb.y);
        r.z = fmaf(dv, acc.z, bb.z);
        r.w = fmaf(dv, acc.w, bb.w);
        r.x = fmaxf(r.x, 0.f) * dv;
        r.y = fmaxf(r.y, 0.f) * dv;
        r.z = fmaxf(r.z, 0.f) * dv;
        r.w = fmaxf(r.w, 0.f) * dv;
        ((uint2*)g_x2b)[w * 32 + lane] = f4_to_bf4(r);
    } else {
        float4 r = make_float4(dv * acc.x, dv * acc.y, dv * acc.z, dv * acc.w);
        ((float4*)g_y)[w * 32 + lane] = r;
    }
}

// ---------------- fused pool + out-GEMM: one block per graph ----------------
// out[g] = mean_{i in graph g}(y_i) @ W2 + b2   (empty graph -> 0)
__device__ __forceinline__ int lower_bound_dev(const int* a, int n, int key) {
    int lo = 0, hi = n;
    while (lo < hi) {
        int mid = (lo + hi) >> 1;
        if (a[mid] < key) lo = mid + 1; else hi = mid;
    }
    return lo;
}

__global__ void __launch_bounds__(512) poolout_kernel(const int* __restrict__ batch,
                                                      const float* __restrict__ W2,
                                                      const float* __restrict__ b2,
                                                      float* __restrict__ out) {
    __shared__ float zrow[128];
    __shared__ float red[4][128];
    __shared__ int s_lo, s_hi;
    int g = blockIdx.x;
    int t = threadIdx.x;
    int f   = t & 127;   // feature
    int seg = t >> 7;    // slice 0..3
    if (t == 0) {
        s_lo = lower_bound_dev(batch, NN, g);
        s_hi = lower_bound_dev(batch, NN, g + 1);
    }
    __syncthreads();
    int lo = s_lo, hi = s_hi;
    // pool
    float sum = 0.f;
    for (int r = lo + seg; r < hi; r += 4) sum += g_y[r * 128 + f];
    red[seg][f] = sum;
    __syncthreads();
    if (seg == 0) {
        float c = (float)(hi - lo);
        zrow[f] = (red[0][f] + red[1][f] + red[2][f] + red[3][f]) / fmaxf(c, 1.0f);
    }
    __syncthreads();
    // gemm: 4-way k-split dot with W2
    float acc = 0.f;
    int k0 = seg * 32;
#pragma unroll
    for (int kk = 0; kk < 32; kk++) {
        int k = k0 + kk;
        acc = fmaf(zrow[k], W2[k * 128 + f], acc);
    }
    red[seg][f] = acc;
    __syncthreads();
    if (seg == 0) {
        float r = (hi > lo)
                ? (red[0][f] + red[1][f] + red[2][f] + red[3][f] + b2[f])
                : 0.0f;   // empty graph: reference yields exactly 0
        out[g * 128 + f] = r;
    }
}

// ---------------- launch ----------------
extern "C" void kernel_launch(void* const* d_in, const int* in_sizes, int n_in,
                              void* d_out, int out_size) {
    const float* x     = (const float*)d_in[0];
    const int*   ei    = (const int*)d_in[1];   // [2, E] row-major
    const int*   batch = (const int*)d_in[2];
    const float* W1    = (const float*)d_in[3];
    const float* b1    = (const float*)d_in[4];
    const float* W2    = (const float*)d_in[5];
    const float* b2    = (const float*)d_in[6];
    float* out = (float*)d_out;

    const int* src = ei;        // edge_index[0]
    const int* dst = ei + NE;   // edge_index[1]

    // One-time host resources (streams/events are not device memory).
    static cudaStream_t s2 = nullptr;
    static cudaEvent_t evFork = nullptr, evJoin = nullptr;
    if (s2 == nullptr) {
        cudaStreamCreateWithFlags(&s2, cudaStreamNonBlocking);
        cudaEventCreateWithFlags(&evFork, cudaEventDisableTiming);
        cudaEventCreateWithFlags(&evJoin, cudaEventDisableTiming);
    }

    // Fork: GEMM-1 (no dependence on edges/dinv) runs on s2 while the CSR
    // build runs on the main stream.
    cudaEventRecord(evFork, 0);
    cudaStreamWaitEvent(s2, evFork, 0);
    gemm_kernel<<<(NN + 127) / 128, 256, 0, s2>>>(x, W1);
    cudaEventRecord(evJoin, s2);

    // CSR build (by destination) + dinv. g_deg and g_flagv are zero on entry
    // (zero-init on first call; re-zeroed by agg1 on every call).
    hist_kernel<<<(NE + 255) / 256, 256>>>(dst);
    scan_kernel<<<NSCAN, SCAN_B>>>();
    fill_kernel<<<(NE + 255) / 256, 256>>>(src, dst);

    // Join: aggregation needs both GEMM-1 output and the CSR.
    cudaStreamWaitEvent(0, evJoin, 0);

    // Layer 1 aggregation (+relu, +b1), writes dinv-prescaled bf16 x2.
    agg_kernel<1><<<(NN + 7) / 8, 256>>>(b1);

    // Layer 2 aggregation only (W2 commuted past S and pooling), writes g_y.
    agg_kernel<2><<<(NN + 7) / 8, 256>>>(nullptr);

    // Fused global-mean-pool + (z @ W2 + b2)
    poolout_kernel<<<NG, 512>>>(batch, W2, b2, out);
}

// round 11
// speedup vs baseline: 1.8452x; 1.0013x over previous
#include <cuda_runtime.h>
#include <cuda_bf16.h>

// Problem constants (fixed by the reference)
constexpr int NN = 40000;   // nodes
constexpr int NE = 640000;  // edges
constexpr int DD = 128;     // feature dim
constexpr int NG = 64;      // graphs

constexpr int SCAN_B = 1024;
constexpr int NSCAN  = (NN + SCAN_B) / SCAN_B;  // 40 blocks, block 39 covers i=NN

// ---------------- scratch (static device globals; no allocations) ----------------
__device__ __nv_bfloat16 g_hb [NN * DD];  // gemm1 out (unscaled, bf16)
__device__ __nv_bfloat16 g_x2b[NN * DD];  // agg1 out (dinv-prescaled relu, bf16)
__device__ float g_y  [NN * DD];          // agg2 out (fp32)
__device__ int   g_deg[NN];               // in-degree (zeroed by agg1 for next replay)
__device__ float g_dinv[NN];              // 1/sqrt(deg+1)
__device__ int   g_rowptr[NN + 1];        // CSR row pointers (by dst)
__device__ int   g_cnt[NN];               // fill cursors
__device__ int   g_csr[NE];               // CSR column indices (src node per edge)
__device__ int   g_bsum[64];              // scan block aggregates
__device__ int   g_flagv[64];             // scan lookback flags (zeroed by agg1)

// ---------------- packed f32x2 helpers ----------------
__device__ __forceinline__ unsigned long long pack2(float lo, float hi) {
    unsigned long long r;
    asm("mov.b64 %0, {%1, %2};" : "=l"(r) : "f"(lo), "f"(hi));
    return r;
}
__device__ __forceinline__ void unpack2(unsigned long long v, float& lo, float& hi) {
    asm("mov.b64 {%0, %1}, %2;" : "=f"(lo), "=f"(hi) : "l"(v));
}
__device__ __forceinline__ unsigned long long fma2(unsigned long long a,
                                                   unsigned long long b,
                                                   unsigned long long c) {
    unsigned long long d;
    asm("fma.rn.f32x2 %0, %1, %2, %3;" : "=l"(d) : "l"(a), "l"(b), "l"(c));
    return d;
}

// ---------------- bf16x4 helpers ----------------
__device__ __forceinline__ float4 bf4_to_f4(uint2 p) {
    __nv_bfloat162 a = *reinterpret_cast<__nv_bfloat162*>(&p.x);
    __nv_bfloat162 b = *reinterpret_cast<__nv_bfloat162*>(&p.y);
    float2 f0 = __bfloat1622float2(a);
    float2 f1 = __bfloat1622float2(b);
    return make_float4(f0.x, f0.y, f1.x, f1.y);
}
__device__ __forceinline__ uint2 f4_to_bf4(float4 v) {
    __nv_bfloat162 a = __float22bfloat162_rn(make_float2(v.x, v.y));
    __nv_bfloat162 b = __float22bfloat162_rn(make_float2(v.z, v.w));
    uint2 r;
    r.x = *reinterpret_cast<unsigned*>(&a);
    r.y = *reinterpret_cast<unsigned*>(&b);
    return r;
}

// ---------------- CSR construction ----------------
__global__ void hist_kernel(const int* __restrict__ dst) {
    int i = blockIdx.x * blockDim.x + threadIdx.x;
    if (i < NE) atomicAdd(&g_deg[dst[i]], 1);
}

// Single-pass scan with decoupled lookback (40 blocks, all co-resident in
// wave 1 so cross-block spinning is safe). Replaces scan1+scan3. Writes
// rowptr, fill cursors, dinv. Flags/bsum zeroed by previous replay's agg1.
__global__ void __launch_bounds__(SCAN_B) scan_kernel() {
    __shared__ int wsum[32];
    __shared__ int s_off;
    int tid = threadIdx.x, lane = tid & 31, wid = tid >> 5;
    int b = blockIdx.x;
    int i = b * SCAN_B + tid;
    int v = (i < NN) ? g_deg[i] : 0;
    int inc = v;
#pragma unroll
    for (int off = 1; off < 32; off <<= 1) {
        int n = __shfl_up_sync(0xFFFFFFFFu, inc, off);
        if (lane >= off) inc += n;
    }
    if (lane == 31) wsum[wid] = inc;
    __syncthreads();
    if (wid == 0) {
        // scan the 32 warp sums; publish block aggregate ASAP
        int s = wsum[lane];
        int si = s;
#pragma unroll
        for (int off = 1; off < 32; off <<= 1) {
            int n = __shfl_up_sync(0xFFFFFFFFu, si, off);
            if (lane >= off) si += n;
        }
        int total = __shfl_sync(0xFFFFFFFFu, si, 31);
        if (lane == 0) {
            g_bsum[b] = total;
            __threadfence();
            *(volatile int*)&g_flagv[b] = 1;
        }
        wsum[lane] = si - s;  // exclusive warp offsets
        // lookback over predecessors
        int a = 0;
        if (b > 0) {
            bool n0 = lane < b;
            bool n1 = lane + 32 < b;
            volatile int* fl = (volatile int*)g_flagv;
            while (true) {
                int f0 = n0 ? fl[lane] : 1;
                int f1 = n1 ? fl[lane + 32] : 1;
                if (__all_sync(0xFFFFFFFFu, (f0 != 0) && (f1 != 0))) break;
            }
            __threadfence();
            a = (n0 ? g_bsum[lane] : 0) + (n1 ? g_bsum[lane + 32] : 0);
#pragma unroll
            for (int off = 16; off; off >>= 1)
                a += __shfl_down_sync(0xFFFFFFFFu, a, off);
        }
        if (lane == 0) s_off = a;
    }
    __syncthreads();
    int excl = inc - v + wsum[wid] + s_off;
    if (i <= NN) {
        g_rowptr[i] = excl;
        if (i < NN) {
            g_cnt[i]  = excl;
            g_dinv[i] = rsqrtf((float)(v + 1));  // +1: self loop
        }
    }
}

__global__ void fill_kernel(const int* __restrict__ src, const int* __restrict__ dst) {
    int i = blockIdx.x * blockDim.x + threadIdx.x;
    if (i < NE) {
        int slot = atomicAdd(&g_cnt[dst[i]], 1);
        g_csr[slot] = src[i];
    }
}

// ---------------- GEMM-1: g_hb = bf16(x @ W1) ----------------
// R4-proven config: 128x128 tile, 256 threads, 8x8/thread, f32x2 mainloop.
__global__ void __launch_bounds__(256) gemm_kernel(const float* __restrict__ A,
                                                   const float* __restrict__ W) {
    __shared__ float As[16][132];
    __shared__ float Bs[16][128];

    int tid = threadIdx.x;
    int tx = tid & 15;
    int ty = tid >> 4;
    int rowBase = blockIdx.x * 128;

    unsigned long long acc2[8][4];
#pragma unroll
    for (int i = 0; i < 8; i++)
#pragma unroll
        for (int j = 0; j < 4; j++) acc2[i][j] = 0ull;

    for (int kt = 0; kt < 128; kt += 16) {
#pragma unroll
        for (int l = 0; l < 2; l++) {
            int idx = tid + l * 256;
            int r   = idx >> 2;
            int k4  = (idx & 3) << 2;
            float4 v = make_float4(0.f, 0.f, 0.f, 0.f);
            int gr = rowBase + r;
            if (gr < NN) v = *(const float4*)(A + gr * 128 + kt + k4);
            As[k4 + 0][r] = v.x;
            As[k4 + 1][r] = v.y;
            As[k4 + 2][r] = v.z;
            As[k4 + 3][r] = v.w;
        }
#pragma unroll
        for (int l = 0; l < 2; l++) {
            int idx = tid + l * 256;
            int kk  = idx >> 5;
            int n4  = (idx & 31) << 2;
            *(float4*)&Bs[kk][n4] = *(const float4*)(W + (kt + kk) * 128 + n4);
        }
        __syncthreads();

#pragma unroll
        for (int k = 0; k < 16; k++) {
            float4 a0 = *(const float4*)&As[k][ty * 8];
            float4 a1 = *(const float4*)&As[k][ty * 8 + 4];
            unsigned long long ad[8];
            ad[0] = pack2(a0.x, a0.x); ad[1] = pack2(a0.y, a0.y);
            ad[2] = pack2(a0.z, a0.z); ad[3] = pack2(a0.w, a0.w);
            ad[4] = pack2(a1.x, a1.x); ad[5] = pack2(a1.y, a1.y);
            ad[6] = pack2(a1.z, a1.z); ad[7] = pack2(a1.w, a1.w);
            ulonglong2 bp0 = *(const ulonglong2*)&Bs[k][tx * 4];
            ulonglong2 bp1 = *(const ulonglong2*)&Bs[k][tx * 4 + 64];
            unsigned long long bd[4] = {bp0.x, bp0.y, bp1.x, bp1.y};
#pragma unroll
            for (int i = 0; i < 8; i++)
#pragma unroll
                for (int j = 0; j < 4; j++)
                    acc2[i][j] = fma2(ad[i], bd[j], acc2[i][j]);
        }
        __syncthreads();
    }

#pragma unroll
    for (int i = 0; i < 8; i++) {
        int gr = rowBase + ty * 8 + i;
        if (gr < NN) {
            float o[8];
#pragma unroll
            for (int j = 0; j < 4; j++) {
                float lo, hi;
                unpack2(acc2[i][j], lo, hi);
                o[2 * j]     = lo;
                o[2 * j + 1] = hi;
            }
            uint2 p0 = f4_to_bf4(make_float4(o[0], o[1], o[2], o[3]));
            uint2 p1 = f4_to_bf4(make_float4(o[4], o[5], o[6], o[7]));
            *(uint2*)(g_hb + gr * 128 + tx * 4)      = p0;
            *(uint2*)(g_hb + gr * 128 + tx * 4 + 64) = p1;
        }
    }
}

// ---------------- aggregation: warp per node, bf16 gathers ----------------
// LAYER==1: in = g_hb. x2 = relu(dinv_i*(dinv_i*h_i + sum dinv_j*h_j) + b1),
//           stores bf16(dinv_i * x2). Also re-zeros g_deg/g_flagv for the
//           next graph replay (their last readers have completed).
// LAYER==2: in = g_x2b (pre-scaled). y_i = dinv_i*(x2s_i + sum x2s_j) -> g_y.
template <int LAYER>
__global__ void __launch_bounds__(256) agg_kernel(const float* __restrict__ bias) {
    int t = blockIdx.x * blockDim.x + threadIdx.x;
    if (LAYER == 1) {
        // maintain zero-invariant for next replay (deg, lookback flags)
        if (t < NN) g_deg[t] = 0;
        if (t < 64) g_flagv[t] = 0;
    }
    int w    = t >> 5;
    int lane = threadIdx.x & 31;
    if (w >= NN) return;

    int beg = g_rowptr[w];
    int end = g_rowptr[w + 1];
    float dv = g_dinv[w];

    const uint2* hv = (LAYER == 1) ? (const uint2*)g_hb : (const uint2*)g_x2b;
    float4 self = bf4_to_f4(hv[w * 32 + lane]);
    float4 acc;
    if (LAYER == 1) {
        acc = make_float4(self.x * dv, self.y * dv, self.z * dv, self.w * dv);
    } else {
        acc = self;
    }

    int k = beg;
    for (; k + 3 < end; k += 4) {
        int s0 = g_csr[k];
        int s1 = g_csr[k + 1];
        int s2 = g_csr[k + 2];
        int s3 = g_csr[k + 3];
        float4 v0 = bf4_to_f4(hv[s0 * 32 + lane]);
        float4 v1 = bf4_to_f4(hv[s1 * 32 + lane]);
        float4 v2 = bf4_to_f4(hv[s2 * 32 + lane]);
        float4 v3 = bf4_to_f4(hv[s3 * 32 + lane]);
        if (LAYER == 1) {
            float d0 = __ldg(&g_dinv[s0]);
            float d1 = __ldg(&g_dinv[s1]);
            float d2 = __ldg(&g_dinv[s2]);
            float d3 = __ldg(&g_dinv[s3]);
            acc.x = fmaf(v0.x, d0, acc.x); acc.y = fmaf(v0.y, d0, acc.y);
            acc.z = fmaf(v0.z, d0, acc.z); acc.w = fmaf(v0.w, d0, acc.w);
            acc.x = fmaf(v1.x, d1, acc.x); acc.y = fmaf(v1.y, d1, acc.y);
            acc.z = fmaf(v1.z, d1, acc.z); acc.w = fmaf(v1.w, d1, acc.w);
            acc.x = fmaf(v2.x, d2, acc.x); acc.y = fmaf(v2.y, d2, acc.y);
            acc.z = fmaf(v2.z, d2, acc.z); acc.w = fmaf(v2.w, d2, acc.w);
            acc.x = fmaf(v3.x, d3, acc.x); acc.y = fmaf(v3.y, d3, acc.y);
            acc.z = fmaf(v3.z, d3, acc.z); acc.w = fmaf(v3.w, d3, acc.w);
        } else {
            acc.x += v0.x + v1.x + v2.x + v3.x;
            acc.y += v0.y + v1.y + v2.y + v3.y;
            acc.z += v0.z + v1.z + v2.z + v3.z;
            acc.w += v0.w + v1.w + v2.w + v3.w;
        }
    }
    for (; k < end; k++) {
        int s = g_csr[k];
        float4 v = bf4_to_f4(hv[s * 32 + lane]);
        if (LAYER == 1) {
            float d = __ldg(&g_dinv[s]);
            acc.x = fmaf(v.x, d, acc.x); acc.y = fmaf(v.y, d, acc.y);
            acc.z = fmaf(v.z, d, acc.z); acc.w = fmaf(v.w, d, acc.w);
        } else {
            acc.x += v.x; acc.y += v.y; acc.z += v.z; acc.w += v.w;
        }
    }

    if (LAYER == 1) {
        float4 bb = ((const float4*)bias)[lane];
        float4 r;
        r.x = fmaf(dv, acc.x, bb.x);
        r.y = fmaf(dv, acc.y, bb.y);
        r.z = fmaf(dv, acc.z, bb.z);
        r.w = fmaf(dv, acc.w, bb.w);
        r.x = fmaxf(r.x, 0.f) * dv;
        r.y = fmaxf(r.y, 0.f) * dv;
        r.z = fmaxf(r.z, 0.f) * dv;
        r.w = fmaxf(r.w, 0.f) * dv;
        ((uint2*)g_x2b)[w * 32 + lane] = f4_to_bf4(r);
    } else {
        float4 r = make_float4(dv * acc.x, dv * acc.y, dv * acc.z, dv * acc.w);
        ((float4*)g_y)[w * 32 + lane] = r;
    }
}

// ---------------- fused pool + out-GEMM: one block per graph ----------------
// out[g] = mean_{i in graph g}(y_i) @ W2 + b2   (empty graph -> 0)
__device__ __forceinline__ int lower_bound_dev(const int* a, int n, int key) {
    int lo = 0, hi = n;
    while (lo < hi) {
        int mid = (lo + hi) >> 1;
        if (a[mid] < key) lo = mid + 1; else hi = mid;
    }
    return lo;
}

__global__ void __launch_bounds__(512) poolout_kernel(const int* __restrict__ batch,
                                                      const float* __restrict__ W2,
                                                      const float* __restrict__ b2,
                                                      float* __restrict__ out) {
    __shared__ float zrow[128];
    __shared__ float red[4][128];
    __shared__ int s_lo, s_hi;
    int g = blockIdx.x;
    int t = threadIdx.x;
    int f   = t & 127;   // feature
    int seg = t >> 7;    // slice 0..3
    if (t == 0) {
        s_lo = lower_bound_dev(batch, NN, g);
        s_hi = lower_bound_dev(batch, NN, g + 1);
    }
    __syncthreads();
    int lo = s_lo, hi = s_hi;
    // pool
    float sum = 0.f;
    for (int r = lo + seg; r < hi; r += 4) sum += g_y[r * 128 + f];
    red[seg][f] = sum;
    __syncthreads();
    if (seg == 0) {
        float c = (float)(hi - lo);
        zrow[f] = (red[0][f] + red[1][f] + red[2][f] + red[3][f]) / fmaxf(c, 1.0f);
    }
    __syncthreads();
    // gemm: 4-way k-split dot with W2
    float acc = 0.f;
    int k0 = seg * 32;
#pragma unroll
    for (int kk = 0; kk < 32; kk++) {
        int k = k0 + kk;
        acc = fmaf(zrow[k], W2[k * 128 + f], acc);
    }
    red[seg][f] = acc;
    __syncthreads();
    if (seg == 0) {
        float r = (hi > lo)
                ? (red[0][f] + red[1][f] + red[2][f] + red[3][f] + b2[f])
                : 0.0f;   // empty graph: reference yields exactly 0
        out[g * 128 + f] = r;
    }
}

// ---------------- launch ----------------
extern "C" void kernel_launch(void* const* d_in, const int* in_sizes, int n_in,
                              void* d_out, int out_size) {
    const float* x     = (const float*)d_in[0];
    const int*   ei    = (const int*)d_in[1];   // [2, E] row-major
    const int*   batch = (const int*)d_in[2];
    const float* W1    = (const float*)d_in[3];
    const float* b1    = (const float*)d_in[4];
    const float* W2    = (const float*)d_in[5];
    const float* b2    = (const float*)d_in[6];
    float* out = (float*)d_out;

    const int* src = ei;        // edge_index[0]
    const int* dst = ei + NE;   // edge_index[1]

    // One-time host resources (streams/events are not device memory).
    static cudaStream_t s2 = nullptr;
    static cudaEvent_t evFork = nullptr, evJoin = nullptr;
    if (s2 == nullptr) {
        cudaStreamCreateWithFlags(&s2, cudaStreamNonBlocking);
        cudaEventCreateWithFlags(&evFork, cudaEventDisableTiming);
        cudaEventCreateWithFlags(&evJoin, cudaEventDisableTiming);
    }

    // Fork: GEMM-1 (no dependence on edges/dinv) runs on s2 while the CSR
    // build runs on the main stream.
    cudaEventRecord(evFork, 0);
    cudaStreamWaitEvent(s2, evFork, 0);
    gemm_kernel<<<(NN + 127) / 128, 256, 0, s2>>>(x, W1);
    cudaEventRecord(evJoin, s2);

    // CSR build (by destination) + dinv. g_deg and g_flagv are zero on entry
    // (zero-init on first call; re-zeroed by agg1 on every call).
    hist_kernel<<<(NE + 255) / 256, 256>>>(dst);
    scan_kernel<<<NSCAN, SCAN_B>>>();
    fill_kernel<<<(NE + 255) / 256, 256>>>(src, dst);

    // Join: aggregation needs both GEMM-1 output and the CSR.
    cudaStreamWaitEvent(0, evJoin, 0);

    // Layer 1 aggregation (+relu, +b1), writes dinv-prescaled bf16 x2.
    agg_kernel<1><<<(NN + 7) / 8, 256>>>(b1);

    // Layer 2 aggregation only (W2 commuted past S and pooling), writes g_y.
    agg_kernel<2><<<(NN + 7) / 8, 256>>>(nullptr);

    // Fused global-mean-pool + (z @ W2 + b2)
    poolout_kernel<<<NG, 512>>>(batch, W2, b2, out);
}